// round 5
// baseline (speedup 1.0000x reference)
#include <cuda_runtime.h>
#include <cstdint>

// Problem constants (shapes fixed by the dataset)
#define NMAX   50000
#define EMAX   640000
#define S_DIM  128
#define DN_DIM 128
#define DA_DIM 64
#define H1     512
#define K1     576      // 2*S + 2*DN + DA
#define K2     512
#define KO     256
#define OUT_C  7
#define MAX_IT 10
#define THR2   1e-4f    // THR^2, compare dist^2 > THR^2 * norm^2

// ---------------------------------------------------------------------------
// Device-global scratch (allocation-free rule: __device__ arrays)
// ---------------------------------------------------------------------------
__device__ float g_state    [NMAX * S_DIM];
__device__ float g_state_old[NMAX * S_DIM];
__device__ float g_new      [NMAX * S_DIM];
__device__ float g_aggst    [NMAX * S_DIM];
__device__ float g_aggnd    [NMAX * DN_DIM];
__device__ float g_aggarc   [NMAX * DA_DIM];
__device__ float g_H        [NMAX * H1];
__device__ int   g_active;
__device__ int   g_flag;

// ---------------------------------------------------------------------------
// Packed f32x2 helpers (FFMA2: 2x fp32 throughput on sm_103a; ptxas never
// auto-fuses — PTX-only path per SASS_QUICKREF)
// ---------------------------------------------------------------------------
__device__ __forceinline__ unsigned long long pk2(float lo, float hi) {
    unsigned long long r;
    asm("mov.b64 %0, {%1, %2};" : "=l"(r) : "f"(lo), "f"(hi));
    return r;
}
__device__ __forceinline__ void upk2(unsigned long long v, float& lo, float& hi) {
    asm("mov.b64 {%0, %1}, %2;" : "=f"(lo), "=f"(hi) : "l"(v));
}
__device__ __forceinline__ void ffma2(unsigned long long& d, unsigned long long a,
                                      unsigned long long b) {
    asm("fma.rn.f32x2 %0, %1, %2, %0;" : "+l"(d) : "l"(a), "l"(b));
}

// ---------------------------------------------------------------------------
// Init: state <- state_init, state_old <- 1, zero one-time agg buffers
// ---------------------------------------------------------------------------
__global__ void init_kernel(const float* __restrict__ state_init, int n) {
    int i = blockIdx.x * blockDim.x + threadIdx.x;
    if (i == 0) { g_active = 1; g_flag = 1; }
    if (i < n * S_DIM) {
        g_state[i]     = state_init[i];
        g_state_old[i] = 1.0f;
        g_aggnd[i]     = 0.0f;
    }
    if (i < n * DA_DIM) g_aggarc[i] = 0.0f;
}

// ---------------------------------------------------------------------------
// Convergence gating: replicate scan's (cont, done) semantics exactly.
// ---------------------------------------------------------------------------
__global__ void conv_pre()  { if (g_active) g_flag = 0; }
__global__ void conv_post() { if (g_active && g_flag == 0) g_active = 0; }

__global__ void conv_check(int n) {
    if (g_active == 0) return;
    int node = blockIdx.x * 4 + (threadIdx.x >> 5);
    if (node >= n) return;
    int lane = threadIdx.x & 31;
    float4 s = *(const float4*)(g_state     + (size_t)node * 128 + lane * 4);
    float4 o = *(const float4*)(g_state_old + (size_t)node * 128 + lane * 4);
    float dx = s.x - o.x, dy = s.y - o.y, dz = s.z - o.z, dw = s.w - o.w;
    float d2 = dx*dx + dy*dy + dz*dz + dw*dw;
    float n2 = o.x*o.x + o.y*o.y + o.z*o.z + o.w*o.w;
#pragma unroll
    for (int off = 16; off > 0; off >>= 1) {
        d2 += __shfl_xor_sync(0xffffffffu, d2, off);
        n2 += __shfl_xor_sync(0xffffffffu, n2, off);
    }
    if (lane == 0 && d2 > THR2 * n2) g_flag = 1;   // benign race: only writes 1
}

// ---------------------------------------------------------------------------
// SpMM scatter (atomic). sel=0: nodes -> g_aggnd (ungated, once).
//                        sel=1: g_state -> g_aggst (gated, per iteration).
// Thread = (edge, 4-feature chunk)
// ---------------------------------------------------------------------------
__global__ void spmm_kernel(const float* __restrict__ dense_in,
                            const int* __restrict__ src, const int* __restrict__ dst,
                            const float* __restrict__ vals, int E, int sel) {
    if (sel && g_active == 0) return;
    int idx = blockIdx.x * blockDim.x + threadIdx.x;
    if (idx >= E * 32) return;
    int e = idx >> 5, q = idx & 31;
    int s = src[e], d = dst[e];
    float v = vals[e];
    const float* dense = sel ? g_state : dense_in;
    float* outp        = sel ? g_aggst : g_aggnd;
    float4 x = *(const float4*)(dense + (size_t)s * 128 + q * 4);
    float* o = outp + (size_t)d * 128 + q * 4;
    atomicAdd(o + 0, v * x.x);
    atomicAdd(o + 1, v * x.y);
    atomicAdd(o + 2, v * x.z);
    atomicAdd(o + 3, v * x.w);
}

// agg_arcs = segment_sum(an_vals * arcs[:,2:], an_dst). Row stride 66 floats,
// +2 offset => only 8-byte aligned -> float2 chunks.
__global__ void scatter_arcs_kernel(const float* __restrict__ arcs,
                                    const int* __restrict__ dst,
                                    const float* __restrict__ vals, int E) {
    int idx = blockIdx.x * blockDim.x + threadIdx.x;
    if (idx >= E * 32) return;
    int e = idx >> 5, q = idx & 31;
    int d = dst[e];
    float v = vals[e];
    float2 x = *(const float2*)(arcs + (size_t)e * 66 + 2 + q * 2);
    float* o = g_aggarc + (size_t)d * 64 + q * 2;
    atomicAdd(o + 0, v * x.x);
    atomicAdd(o + 1, v * x.y);
}

__global__ void zero_aggst_kernel(int tot) {
    if (g_active == 0) return;
    int i = blockIdx.x * blockDim.x + threadIdx.x;
    if (i < tot) g_aggst[i] = 0.0f;
}

__global__ void update_kernel(int tot) {
    if (g_active == 0) return;
    int i = blockIdx.x * blockDim.x + threadIdx.x;
    if (i < tot) {
        float s = g_state[i];
        g_state_old[i] = s;
        g_state[i] = g_new[i];
    }
}

// ---------------------------------------------------------------------------
// Fused-gather SGEMM, 128x128x16 tiles, 8x8 per thread, f32x2 accumulators.
// MODE 0: A = g_H (K=512)           -> C = g_new   (layer 2)
// MODE 1: A = [state|nodes|aggst|aggnd|aggarc] (K=576) -> C = g_H (layer 1)
// MODE 2: A = [state|nodes] (K=256) -> C = g_H     (output layer 1)
// Always fused bias + tanh. Ncols must be a multiple of 128 (512/128/512 ok).
// ---------------------------------------------------------------------------
template<int MODE>
__device__ __forceinline__ float4 ldA(const float* __restrict__ nodes, int row, int c) {
    if (MODE == 0) {
        return *(const float4*)(g_H + (size_t)row * K2 + c);
    } else if (MODE == 1) {
        if (c < 128)      return *(const float4*)(g_state  + (size_t)row * 128 + c);
        else if (c < 256) return *(const float4*)(nodes    + (size_t)row * 128 + (c - 128));
        else if (c < 384) return *(const float4*)(g_aggst  + (size_t)row * 128 + (c - 256));
        else if (c < 512) return *(const float4*)(g_aggnd  + (size_t)row * 128 + (c - 384));
        else              return *(const float4*)(g_aggarc + (size_t)row * 64  + (c - 512));
    } else {
        if (c < 128)      return *(const float4*)(g_state  + (size_t)row * 128 + c);
        else              return *(const float4*)(nodes    + (size_t)row * 128 + (c - 128));
    }
}

template<int MODE, bool GATED>
__global__ __launch_bounds__(256, 2) void sgemm_kernel(
    const float* __restrict__ nodes, const float* __restrict__ B,
    const float* __restrict__ bias, int M, int K, int Ncols)
{
    if (GATED && g_active == 0) return;
    float* __restrict__ C = (MODE == 0) ? g_new : g_H;

    __shared__ float As[16][128];   // transposed: As[k][m]
    __shared__ float Bs[16][128];   // Bs[k][n]

    const int tid = threadIdx.x;
    const int tx  = tid & 15;
    const int ty  = tid >> 4;
    const int rowBase = blockIdx.y * 128;
    const int colBase = blockIdx.x * 128;

    const int arow = tid >> 1;          // 0..127
    const int acol = (tid & 1) * 8;     // 0 or 8
    const int grow = rowBase + arow;
    const bool rowOK = grow < M;

    const int brow = tid >> 4;          // 0..15
    const int bcol = (tid & 15) * 8;

    unsigned long long acc[8][4];
#pragma unroll
    for (int i = 0; i < 8; i++)
#pragma unroll
        for (int j = 0; j < 4; j++) acc[i][j] = 0ull;

    for (int k0 = 0; k0 < K; k0 += 16) {
        float4 a0 = make_float4(0.f, 0.f, 0.f, 0.f), a1 = a0;
        if (rowOK) {
            a0 = ldA<MODE>(nodes, grow, k0 + acol);
            a1 = ldA<MODE>(nodes, grow, k0 + acol + 4);
        }
        const float* bp = B + (size_t)(k0 + brow) * Ncols + colBase + bcol;
        float4 b0 = *(const float4*)bp;
        float4 b1 = *(const float4*)(bp + 4);

        __syncthreads();
        As[acol + 0][arow] = a0.x; As[acol + 1][arow] = a0.y;
        As[acol + 2][arow] = a0.z; As[acol + 3][arow] = a0.w;
        As[acol + 4][arow] = a1.x; As[acol + 5][arow] = a1.y;
        As[acol + 6][arow] = a1.z; As[acol + 7][arow] = a1.w;
        *(float4*)&Bs[brow][bcol]     = b0;
        *(float4*)&Bs[brow][bcol + 4] = b1;
        __syncthreads();

#pragma unroll
        for (int kk = 0; kk < 16; kk++) {
            float4 av0 = *(const float4*)&As[kk][ty * 8];
            float4 av1 = *(const float4*)&As[kk][ty * 8 + 4];
            float4 bv0 = *(const float4*)&Bs[kk][tx * 8];
            float4 bv1 = *(const float4*)&Bs[kk][tx * 8 + 4];
            unsigned long long bb[4] = { pk2(bv0.x, bv0.y), pk2(bv0.z, bv0.w),
                                         pk2(bv1.x, bv1.y), pk2(bv1.z, bv1.w) };
            float am[8] = { av0.x, av0.y, av0.z, av0.w, av1.x, av1.y, av1.z, av1.w };
#pragma unroll
            for (int mi = 0; mi < 8; mi++) {
                unsigned long long aa = pk2(am[mi], am[mi]);
#pragma unroll
                for (int ni = 0; ni < 4; ni++) ffma2(acc[mi][ni], aa, bb[ni]);
            }
        }
    }

#pragma unroll
    for (int mi = 0; mi < 8; mi++) {
        int r = rowBase + ty * 8 + mi;
        if (r < M) {
            float* cp        = C + (size_t)r * Ncols + colBase + tx * 8;
            const float* bp2 = bias + colBase + tx * 8;
#pragma unroll
            for (int ni = 0; ni < 4; ni++) {
                float lo, hi;
                upk2(acc[mi][ni], lo, hi);
                lo = tanhf(lo + bp2[ni * 2]);
                hi = tanhf(hi + bp2[ni * 2 + 1]);
                cp[ni * 2]     = lo;
                cp[ni * 2 + 1] = hi;
            }
        }
    }
}

// ---------------------------------------------------------------------------
// Output head: out[n,7] = (g_H[n,512] @ Wo2[512,7] + bo2) * mask
// One warp per row; Wo2 staged in shared (14KB).
// Masks are int32 (bool -> i32 in harness; established by the sqrt(3/4)
// rel-err signature in R3).
// ---------------------------------------------------------------------------
__global__ void out_kernel(const float* __restrict__ Wo2, const float* __restrict__ bo2,
                           const int* __restrict__ m1,
                           const int* __restrict__ m2,
                           float* __restrict__ out, int n) {
    __shared__ float w[K2 * OUT_C];
    __shared__ float b[OUT_C];
    for (int i = threadIdx.x; i < K2 * OUT_C; i += blockDim.x) w[i] = Wo2[i];
    if (threadIdx.x < OUT_C) b[threadIdx.x] = bo2[threadIdx.x];
    __syncthreads();

    int row = blockIdx.x * 4 + (threadIdx.x >> 5);
    if (row >= n) return;
    int lane = threadIdx.x & 31;

    float acc[OUT_C];
#pragma unroll
    for (int c = 0; c < OUT_C; c++) acc[c] = 0.0f;

    const float* h = g_H + (size_t)row * K2;
    for (int k = lane; k < K2; k += 32) {
        float hv = h[k];
        const float* wr = w + k * OUT_C;
#pragma unroll
        for (int c = 0; c < OUT_C; c++) acc[c] += hv * wr[c];
    }
#pragma unroll
    for (int c = 0; c < OUT_C; c++)
#pragma unroll
        for (int off = 16; off > 0; off >>= 1)
            acc[c] += __shfl_xor_sync(0xffffffffu, acc[c], off);

    if (lane == 0) {
        float msk = (m1[row] != 0 && m2[row] != 0) ? 1.0f : 0.0f;
#pragma unroll
        for (int c = 0; c < OUT_C; c++) out[(size_t)row * OUT_C + c] = (acc[c] + b[c]) * msk;
    }
}

// ---------------------------------------------------------------------------
// Launch
// ---------------------------------------------------------------------------
extern "C" void kernel_launch(void* const* d_in, const int* in_sizes, int n_in,
                              void* d_out, int out_size) {
    const float* nodes          = (const float*)d_in[0];
    const float* arcs           = (const float*)d_in[1];
    const int*   m1             = (const int*)d_in[2];
    const int*   m2             = (const int*)d_in[3];
    const int*   adj_src        = (const int*)d_in[4];
    const int*   adj_dst        = (const int*)d_in[5];
    const float* adj_vals       = (const float*)d_in[6];
    const int*   an_dst         = (const int*)d_in[7];
    const float* an_vals        = (const float*)d_in[8];
    const float* state_init     = (const float*)d_in[9];
    const float* Ws1            = (const float*)d_in[10];
    const float* bs1            = (const float*)d_in[11];
    const float* Ws2            = (const float*)d_in[12];
    const float* bs2            = (const float*)d_in[13];
    const float* Wo1            = (const float*)d_in[14];
    const float* bo1            = (const float*)d_in[15];
    const float* Wo2            = (const float*)d_in[16];
    const float* bo2            = (const float*)d_in[17];

    const int n = in_sizes[0] / DN_DIM;   // 50000
    const int E = in_sizes[4];            // 640000
    float* out = (float*)d_out;

    const int elemBlocks = (n * S_DIM + 255) / 256;
    const int edgeBlocks = (E * 32 + 255) / 256;

    // One-time setup
    init_kernel<<<elemBlocks, 256>>>(state_init, n);
    scatter_arcs_kernel<<<edgeBlocks, 256>>>(arcs, an_dst, an_vals, E);
    spmm_kernel<<<edgeBlocks, 256>>>(nodes, adj_src, adj_dst, adj_vals, E, 0);

    dim3 g1(H1 / 128, (n + 127) / 128);     // 4 x 391
    dim3 g2(S_DIM / 128, (n + 127) / 128);  // 1 x 391

    for (int it = 0; it < MAX_IT; it++) {
        conv_pre<<<1, 1>>>();
        conv_check<<<(n + 3) / 4, 128>>>(n);
        conv_post<<<1, 1>>>();
        zero_aggst_kernel<<<elemBlocks, 256>>>(n * S_DIM);
        spmm_kernel<<<edgeBlocks, 256>>>(nullptr, adj_src, adj_dst, adj_vals, E, 1);
        sgemm_kernel<1, true><<<g1, 256>>>(nodes, Ws1, bs1, n, K1, H1);
        sgemm_kernel<0, true><<<g2, 256>>>(nodes, Ws2, bs2, n, K2, S_DIM);
        update_kernel<<<elemBlocks, 256>>>(n * S_DIM);
    }

    sgemm_kernel<2, false><<<g1, 256>>>(nodes, Wo1, bo1, n, KO, H1);
    out_kernel<<<(n + 3) / 4, 128>>>(Wo2, bo2, m1, m2, out, n);
}

// round 14
// speedup vs baseline: 1.0986x; 1.0986x over previous
#include <cuda_runtime.h>
#include <cuda_bf16.h>
#include <mma.h>
#include <cstdint>

using namespace nvcuda;

// Problem constants
#define NMAX   50000
#define EMAX   640000
#define S_DIM  128
#define DN_DIM 128
#define DA_DIM 64
#define H1     512
#define K1     576
#define K2     512
#define KO     256
#define OUT_C  7
#define MAX_IT 10
#define THR2   1e-4f

#define SCAN_CHUNK 1024
#define NCHUNK ((NMAX + SCAN_CHUNK - 1) / SCAN_CHUNK)   // 49

// ---------------------------------------------------------------------------
// Device-global scratch (NEVER pass these as kernel args from host — the host
// name is a shadow symbol; GB300 ATS makes that bug silent. Reference them
// from device code only.)
// ---------------------------------------------------------------------------
__device__ float g_state    [NMAX * S_DIM];
__device__ float g_state_old[NMAX * S_DIM];
__device__ float g_new      [NMAX * S_DIM];
__device__ float g_aggst    [NMAX * S_DIM];
__device__ float g_aggnd    [NMAX * DN_DIM];
__device__ float g_aggarc   [NMAX * DA_DIM];
__device__ float g_H        [NMAX * H1];
__device__ int   g_active;
__device__ int   g_flag;

// CSR (built once per call from adj_src/adj_dst/adj_vals)
__device__ int   g_rowptr[NMAX + 1];
__device__ int   g_fill  [NMAX];
__device__ int   g_chsum [NCHUNK];
__device__ int   g_esrc  [EMAX];
__device__ float g_eval  [EMAX];

// bf16 split operands for tensor-core GEMMs
__device__ __nv_bfloat16 g_Ahi[NMAX * K1];   // [state|nodes|aggst|aggnd|aggarc]
__device__ __nv_bfloat16 g_Alo[NMAX * K1];
__device__ __nv_bfloat16 g_Hhi[NMAX * H1];
__device__ __nv_bfloat16 g_Hlo[NMAX * H1];
__device__ __nv_bfloat16 g_W1h[H1 * K1];     // Ws1^T  [512,576]
__device__ __nv_bfloat16 g_W1l[H1 * K1];
__device__ __nv_bfloat16 g_W2h[S_DIM * K2];  // Ws2^T  [128,512]
__device__ __nv_bfloat16 g_W2l[S_DIM * K2];
__device__ __nv_bfloat16 g_Woh[H1 * KO];     // Wo1^T  [512,256]
__device__ __nv_bfloat16 g_Wol[H1 * KO];

__device__ __forceinline__ void split_bf16(float v, __nv_bfloat16& h, __nv_bfloat16& l) {
    h = __float2bfloat16(v);
    l = __float2bfloat16(v - __bfloat162float(h));
}

// ---------------------------------------------------------------------------
// Setup / gating kernels
// ---------------------------------------------------------------------------
__global__ void init_kernel(const float* __restrict__ state_init, int n) {
    int i = blockIdx.x * blockDim.x + threadIdx.x;
    if (i == 0) { g_active = 1; g_flag = 1; }
    if (i < n * S_DIM) {
        g_state[i]     = state_init[i];
        g_state_old[i] = 1.0f;
    }
    if (i < n * DA_DIM) g_aggarc[i] = 0.0f;
    if (i < n) g_fill[i] = 0;            // doubles as histogram counter
}

__global__ void conv_pre()  { if (g_active) g_flag = 0; }
__global__ void conv_post() { if (g_active && g_flag == 0) g_active = 0; }

__global__ void conv_check(int n) {
    if (g_active == 0) return;
    int node = blockIdx.x * 4 + (threadIdx.x >> 5);
    if (node >= n) return;
    int lane = threadIdx.x & 31;
    float4 s = *(const float4*)(g_state     + (size_t)node * 128 + lane * 4);
    float4 o = *(const float4*)(g_state_old + (size_t)node * 128 + lane * 4);
    float dx = s.x - o.x, dy = s.y - o.y, dz = s.z - o.z, dw = s.w - o.w;
    float d2 = dx*dx + dy*dy + dz*dz + dw*dw;
    float n2 = o.x*o.x + o.y*o.y + o.z*o.z + o.w*o.w;
#pragma unroll
    for (int off = 16; off > 0; off >>= 1) {
        d2 += __shfl_xor_sync(0xffffffffu, d2, off);
        n2 += __shfl_xor_sync(0xffffffffu, n2, off);
    }
    if (lane == 0 && d2 > THR2 * n2) g_flag = 1;
}

// ---------------------------------------------------------------------------
// CSR build: histogram -> chunked exclusive scan -> slot fill
// ---------------------------------------------------------------------------
__global__ void csr_count_kernel(const int* __restrict__ dst, int E) {
    int e = blockIdx.x * blockDim.x + threadIdx.x;
    if (e < E) atomicAdd(&g_fill[dst[e]], 1);
}

__global__ void csr_scan1_kernel(int n) {   // NCHUNK blocks x SCAN_CHUNK threads
    __shared__ int s[SCAN_CHUNK];
    int t = threadIdx.x, i = blockIdx.x * SCAN_CHUNK + t;
    int x = (i < n) ? g_fill[i] : 0;
    s[t] = x;
    __syncthreads();
#pragma unroll
    for (int off = 1; off < SCAN_CHUNK; off <<= 1) {
        int v = (t >= off) ? s[t - off] : 0;
        __syncthreads();
        s[t] += v;
        __syncthreads();
    }
    if (i <= n) g_rowptr[i] = s[t] - x;      // exclusive within chunk
    if (t == SCAN_CHUNK - 1) g_chsum[blockIdx.x] = s[t];
}

__global__ void csr_scan2_kernel(int n, int E) {   // 1 thread
    int run = 0;
    for (int c = 0; c < NCHUNK; c++) { int t = g_chsum[c]; g_chsum[c] = run; run += t; }
    g_rowptr[n] = E;
}

__global__ void csr_scan3_kernel(int n) {
    int i = blockIdx.x * blockDim.x + threadIdx.x;
    if (i < n) {
        g_rowptr[i] += g_chsum[i / SCAN_CHUNK];
        g_fill[i] = 0;                        // reset for fill phase
    }
}

__global__ void csr_fill_kernel(const int* __restrict__ src, const int* __restrict__ dst,
                                const float* __restrict__ vals, int E) {
    int e = blockIdx.x * blockDim.x + threadIdx.x;
    if (e >= E) return;
    int d = dst[e];
    int pos = g_rowptr[d] + atomicAdd(&g_fill[d], 1);
    if (pos >= E) pos = E - 1;               // bounds clamp
    g_esrc[pos] = src[e];
    g_eval[pos] = vals[e];
}

// CSR SpMM gather: one warp per node, lane = float4 feature chunk. No atomics.
// MODE 0: nodes (arg) -> g_aggnd, ungated.  MODE 1: g_state -> g_aggst, gated.
// Buffers selected IN DEVICE CODE (device symbols must not cross the host ABI).
template<int MODE>
__global__ void spmm_csr_kernel(const float* __restrict__ nodes_in, int n) {
    if (MODE == 1 && g_active == 0) return;
    int node = blockIdx.x * 8 + (threadIdx.x >> 5);
    if (node >= n) return;
    const float* dense = (MODE == 1) ? g_state : nodes_in;
    float* outp        = (MODE == 1) ? g_aggst : g_aggnd;
    int lane = threadIdx.x & 31;
    int beg = g_rowptr[node], end = g_rowptr[node + 1];
    float4 acc = make_float4(0.f, 0.f, 0.f, 0.f);
    for (int j = beg; j < end; j++) {
        int s   = g_esrc[j];
        float v = g_eval[j];
        float4 x = *(const float4*)(dense + (size_t)s * 128 + lane * 4);
        acc.x += v * x.x; acc.y += v * x.y; acc.z += v * x.z; acc.w += v * x.w;
    }
    *(float4*)(outp + (size_t)node * 128 + lane * 4) = acc;
}

// agg_arcs (one-time): atomic scatter, row stride 66 floats, +2 offset
__global__ void scatter_arcs_kernel(const float* __restrict__ arcs,
                                    const int* __restrict__ dst,
                                    const float* __restrict__ vals, int E) {
    int idx = blockIdx.x * blockDim.x + threadIdx.x;
    if (idx >= E * 32) return;
    int e = idx >> 5, q = idx & 31;
    int d = dst[e];
    float v = vals[e];
    float2 x = *(const float2*)(arcs + (size_t)e * 66 + 2 + q * 2);
    float* o = g_aggarc + (size_t)d * 64 + q * 2;
    atomicAdd(o + 0, v * x.x);
    atomicAdd(o + 1, v * x.y);
}

__global__ void update_kernel(int tot) {
    if (g_active == 0) return;
    int i = blockIdx.x * blockDim.x + threadIdx.x;
    if (i < tot) {
        float s = g_state[i];
        g_state_old[i] = s;
        g_state[i] = g_new[i];
    }
}

// Transpose + bf16-split all weights
#define WTOT (H1*K1 + S_DIM*K2 + H1*KO)
__global__ void wsetup_kernel(const float* __restrict__ Ws1,
                              const float* __restrict__ Ws2,
                              const float* __restrict__ Wo1) {
    int i = blockIdx.x * blockDim.x + threadIdx.x;
    if (i >= WTOT) return;
    if (i < H1 * K1) {
        int nn = i / K1, kk = i % K1;
        split_bf16(Ws1[(size_t)kk * H1 + nn], g_W1h[i], g_W1l[i]);
    } else if (i < H1 * K1 + S_DIM * K2) {
        int j = i - H1 * K1;
        int nn = j / K2, kk = j % K2;
        split_bf16(Ws2[(size_t)kk * S_DIM + nn], g_W2h[j], g_W2l[j]);
    } else {
        int j = i - H1 * K1 - S_DIM * K2;
        int nn = j / KO, kk = j % KO;
        split_bf16(Wo1[(size_t)kk * H1 + nn], g_Woh[j], g_Wol[j]);
    }
}

// Static A cols: nodes -> 128..255, aggnd -> 384..511, aggarc -> 512..575
__global__ void conv_staticA_kernel(const float* __restrict__ nodes, int n) {
    int i = blockIdx.x * blockDim.x + threadIdx.x;
    if (i >= n * 320) return;
    int r = i / 320, c0 = i % 320;
    float v; int col;
    if (c0 < 128)      { v = nodes[(size_t)r * 128 + c0];            col = 128 + c0; }
    else if (c0 < 256) { v = g_aggnd[(size_t)r * 128 + (c0 - 128)];  col = 384 + (c0 - 128); }
    else               { v = g_aggarc[(size_t)r * 64 + (c0 - 256)];  col = 512 + (c0 - 256); }
    size_t o = (size_t)r * K1 + col;
    split_bf16(v, g_Ahi[o], g_Alo[o]);
}

// Dynamic A cols: state -> 0..127, aggst -> 256..383 (gated)
__global__ void conv_dynA_kernel(int n) {
    if (g_active == 0) return;
    int i = blockIdx.x * blockDim.x + threadIdx.x;
    if (i >= n * 256) return;
    int r = i >> 8, c0 = i & 255;
    float v; int col;
    if (c0 < 128) { v = g_state[(size_t)r * 128 + c0];          col = c0; }
    else          { v = g_aggst[(size_t)r * 128 + (c0 - 128)];  col = 256 + (c0 - 128); }
    size_t o = (size_t)r * K1 + col;
    split_bf16(v, g_Ahi[o], g_Alo[o]);
}

// Final state cols refresh for output head (ungated)
__global__ void conv_finalA_kernel(int n) {
    int i = blockIdx.x * blockDim.x + threadIdx.x;
    if (i >= n * 128) return;
    int r = i >> 7, c = i & 127;
    size_t o = (size_t)r * K1 + c;
    split_bf16(g_state[(size_t)r * 128 + c], g_Ahi[o], g_Alo[o]);
}

// ---------------------------------------------------------------------------
// wmma (HMMA) split-bf16 GEMM. CTA tile 128x128, 8 warps, warp tile 64x32.
// ---------------------------------------------------------------------------
#define LDS_B16 72
#define LDC_F32 132
#define OFF_AH  0
#define OFF_AL  (128 * LDS_B16 * 2)
#define OFF_BH  (OFF_AL + 128 * LDS_B16 * 2)
#define OFF_BL  (OFF_BH + 128 * LDS_B16 * 2)
#define SMEM_BYTES (OFF_BL + 128 * LDS_B16 * 2)   // 73728

template<int KTOT, int ASTRIDE, int EPI>
__global__ __launch_bounds__(256)
void tgemm_kernel(const float* __restrict__ bias, int M) {
    if (EPI != 2 && g_active == 0) return;
    extern __shared__ char smem[];
    __nv_bfloat16* sAh = (__nv_bfloat16*)(smem + OFF_AH);
    __nv_bfloat16* sAl = (__nv_bfloat16*)(smem + OFF_AL);
    __nv_bfloat16* sBh = (__nv_bfloat16*)(smem + OFF_BH);
    __nv_bfloat16* sBl = (__nv_bfloat16*)(smem + OFF_BL);

    const int tid = threadIdx.x, wid = tid >> 5;
    const int warpRow = wid >> 2;
    const int warpCol = wid & 3;
    const int rowBase = blockIdx.y * 128, colBase = blockIdx.x * 128;

    const __nv_bfloat16 *Ah, *Al, *Bh, *Bl;
    if (EPI == 0)      { Ah = g_Ahi; Al = g_Alo; Bh = g_W1h; Bl = g_W1l; }
    else if (EPI == 1) { Ah = g_Hhi; Al = g_Hlo; Bh = g_W2h; Bl = g_W2l; }
    else               { Ah = g_Ahi; Al = g_Alo; Bh = g_Woh; Bl = g_Wol; }

    wmma::fragment<wmma::accumulator, 16, 16, 16, float> acc[4][2];
#pragma unroll
    for (int mt = 0; mt < 4; mt++)
#pragma unroll
        for (int nt = 0; nt < 2; nt++)
            wmma::fill_fragment(acc[mt][nt], 0.0f);

    const int lr = tid >> 1, lhalf = (tid & 1) * 32;
    const int grow = rowBase + lr;
    const bool aok = grow < M;
    const int gbrow = colBase + lr;

    for (int k0 = 0; k0 < KTOT; k0 += 64) {
        const __nv_bfloat16* pAh = Ah + (size_t)grow * ASTRIDE + k0 + lhalf;
        const __nv_bfloat16* pAl = Al + (size_t)grow * ASTRIDE + k0 + lhalf;
        const __nv_bfloat16* pBh = Bh + (size_t)gbrow * KTOT + k0 + lhalf;
        const __nv_bfloat16* pBl = Bl + (size_t)gbrow * KTOT + k0 + lhalf;
        __nv_bfloat16* qAh = sAh + lr * LDS_B16 + lhalf;
        __nv_bfloat16* qAl = sAl + lr * LDS_B16 + lhalf;
        __nv_bfloat16* qBh = sBh + lr * LDS_B16 + lhalf;
        __nv_bfloat16* qBl = sBl + lr * LDS_B16 + lhalf;
#pragma unroll
        for (int j = 0; j < 4; j++) {
            uint4 vh = make_uint4(0u, 0u, 0u, 0u), vl = vh;
            if (aok) { vh = *(const uint4*)(pAh + j * 8); vl = *(const uint4*)(pAl + j * 8); }
            *(uint4*)(qAh + j * 8) = vh;
            *(uint4*)(qAl + j * 8) = vl;
            *(uint4*)(qBh + j * 8) = *(const uint4*)(pBh + j * 8);
            *(uint4*)(qBl + j * 8) = *(const uint4*)(pBl + j * 8);
        }
        __syncthreads();

#pragma unroll
        for (int kk = 0; kk < 4; kk++) {
            wmma::fragment<wmma::matrix_b, 16, 16, 16, __nv_bfloat16, wmma::col_major> bh[2], bl[2];
#pragma unroll
            for (int nt = 0; nt < 2; nt++) {
                const __nv_bfloat16* bp = sBh + (warpCol * 32 + nt * 16) * LDS_B16 + kk * 16;
                const __nv_bfloat16* bq = sBl + (warpCol * 32 + nt * 16) * LDS_B16 + kk * 16;
                wmma::load_matrix_sync(bh[nt], bp, LDS_B16);
                wmma::load_matrix_sync(bl[nt], bq, LDS_B16);
            }
#pragma unroll
            for (int mt = 0; mt < 4; mt++) {
                wmma::fragment<wmma::matrix_a, 16, 16, 16, __nv_bfloat16, wmma::row_major> ah, al;
                const __nv_bfloat16* ap = sAh + (warpRow * 64 + mt * 16) * LDS_B16 + kk * 16;
                const __nv_bfloat16* aq = sAl + (warpRow * 64 + mt * 16) * LDS_B16 + kk * 16;
                wmma::load_matrix_sync(ah, ap, LDS_B16);
                wmma::load_matrix_sync(al, aq, LDS_B16);
#pragma unroll
                for (int nt = 0; nt < 2; nt++) {
                    wmma::mma_sync(acc[mt][nt], ah, bh[nt], acc[mt][nt]);
                    wmma::mma_sync(acc[mt][nt], al, bh[nt], acc[mt][nt]);
                    wmma::mma_sync(acc[mt][nt], ah, bl[nt], acc[mt][nt]);
                }
            }
        }
        __syncthreads();
    }

    float* sC = (float*)smem;
#pragma unroll
    for (int mt = 0; mt < 4; mt++)
#pragma unroll
        for (int nt = 0; nt < 2; nt++)
            wmma::store_matrix_sync(sC + (warpRow * 64 + mt * 16) * LDC_F32
                                       + warpCol * 32 + nt * 16,
                                    acc[mt][nt], LDC_F32, wmma::mem_row_major);
    __syncthreads();

    const int er = tid >> 1, ecb = (tid & 1) * 64;
    const int m = rowBase + er;
    if (m < M) {
#pragma unroll 8
        for (int c = 0; c < 64; c++) {
            int col = ecb + c, gcol = colBase + col;
            float v = tanhf(sC[er * LDC_F32 + col] + bias[gcol]);
            if (EPI == 0) {
                __nv_bfloat16 h, l;
                split_bf16(v, h, l);
                g_Hhi[(size_t)m * H1 + gcol] = h;
                g_Hlo[(size_t)m * H1 + gcol] = l;
            } else if (EPI == 1) {
                g_new[(size_t)m * S_DIM + gcol] = v;
            } else {
                g_H[(size_t)m * H1 + gcol] = v;
            }
        }
    }
}

// ---------------------------------------------------------------------------
// Output head (masks are int32)
// ---------------------------------------------------------------------------
__global__ void out_kernel(const float* __restrict__ Wo2, const float* __restrict__ bo2,
                           const int* __restrict__ m1, const int* __restrict__ m2,
                           float* __restrict__ out, int n) {
    __shared__ float w[K2 * OUT_C];
    __shared__ float b[OUT_C];
    for (int i = threadIdx.x; i < K2 * OUT_C; i += blockDim.x) w[i] = Wo2[i];
    if (threadIdx.x < OUT_C) b[threadIdx.x] = bo2[threadIdx.x];
    __syncthreads();

    int row = blockIdx.x * 4 + (threadIdx.x >> 5);
    if (row >= n) return;
    int lane = threadIdx.x & 31;

    float acc[OUT_C];
#pragma unroll
    for (int c = 0; c < OUT_C; c++) acc[c] = 0.0f;
    const float* h = g_H + (size_t)row * K2;
    for (int k = lane; k < K2; k += 32) {
        float hv = h[k];
        const float* wr = w + k * OUT_C;
#pragma unroll
        for (int c = 0; c < OUT_C; c++) acc[c] += hv * wr[c];
    }
#pragma unroll
    for (int c = 0; c < OUT_C; c++)
#pragma unroll
        for (int off = 16; off > 0; off >>= 1)
            acc[c] += __shfl_xor_sync(0xffffffffu, acc[c], off);

    if (lane == 0) {
        float msk = (m1[row] != 0 && m2[row] != 0) ? 1.0f : 0.0f;
#pragma unroll
        for (int c = 0; c < OUT_C; c++) out[(size_t)row * OUT_C + c] = (acc[c] + b[c]) * msk;
    }
}

// ---------------------------------------------------------------------------
// Launch
// ---------------------------------------------------------------------------
extern "C" void kernel_launch(void* const* d_in, const int* in_sizes, int n_in,
                              void* d_out, int out_size) {
    const float* nodes      = (const float*)d_in[0];
    const float* arcs       = (const float*)d_in[1];
    const int*   m1         = (const int*)d_in[2];
    const int*   m2         = (const int*)d_in[3];
    const int*   adj_src    = (const int*)d_in[4];
    const int*   adj_dst    = (const int*)d_in[5];
    const float* adj_vals   = (const float*)d_in[6];
    const int*   an_dst     = (const int*)d_in[7];
    const float* an_vals    = (const float*)d_in[8];
    const float* state_init = (const float*)d_in[9];
    const float* Ws1        = (const float*)d_in[10];
    const float* bs1        = (const float*)d_in[11];
    const float* Ws2        = (const float*)d_in[12];
    const float* bs2        = (const float*)d_in[13];
    const float* Wo1        = (const float*)d_in[14];
    const float* bo1        = (const float*)d_in[15];
    const float* Wo2        = (const float*)d_in[16];
    const float* bo2        = (const float*)d_in[17];

    const int n = in_sizes[0] / DN_DIM;   // 50000
    const int E = in_sizes[4];            // 640000
    float* out = (float*)d_out;

    cudaFuncSetAttribute(tgemm_kernel<K1, K1, 0>, cudaFuncAttributeMaxDynamicSharedMemorySize, SMEM_BYTES);
    cudaFuncSetAttribute(tgemm_kernel<K2, K2, 1>, cudaFuncAttributeMaxDynamicSharedMemorySize, SMEM_BYTES);
    cudaFuncSetAttribute(tgemm_kernel<KO, K1, 2>, cudaFuncAttributeMaxDynamicSharedMemorySize, SMEM_BYTES);

    const int elemBlocks = (n * S_DIM + 255) / 256;
    const int edgeBlocks32 = (E * 32 + 255) / 256;
    const int edgeBlocks  = (E + 255) / 256;
    const int nodeBlocks8 = (n + 7) / 8;
    const int gy = (n + 127) / 128;       // 391

    // One-time setup
    init_kernel<<<elemBlocks, 256>>>(state_init, n);
    scatter_arcs_kernel<<<edgeBlocks32, 256>>>(arcs, an_dst, an_vals, E);
    // CSR build for adjacency
    csr_count_kernel<<<edgeBlocks, 256>>>(adj_dst, E);
    csr_scan1_kernel<<<NCHUNK, SCAN_CHUNK>>>(n);
    csr_scan2_kernel<<<1, 1>>>(n, E);
    csr_scan3_kernel<<<(n + 255) / 256, 256>>>(n);
    csr_fill_kernel<<<edgeBlocks, 256>>>(adj_src, adj_dst, adj_vals, E);
    // One-time aggregations + weight prep
    spmm_csr_kernel<0><<<nodeBlocks8, 256>>>(nodes, n);
    wsetup_kernel<<<(WTOT + 255) / 256, 256>>>(Ws1, Ws2, Wo1);
    conv_staticA_kernel<<<(n * 320 + 255) / 256, 256>>>(nodes, n);

    for (int it = 0; it < MAX_IT; it++) {
        conv_pre<<<1, 1>>>();
        conv_check<<<(n + 3) / 4, 128>>>(n);
        conv_post<<<1, 1>>>();
        spmm_csr_kernel<1><<<nodeBlocks8, 256>>>(nullptr, n);
        conv_dynA_kernel<<<(n * 256 + 255) / 256, 256>>>(n);
        tgemm_kernel<K1, K1, 0><<<dim3(4, gy), 256, SMEM_BYTES>>>(bs1, n);
        tgemm_kernel<K2, K2, 1><<<dim3(1, gy), 256, SMEM_BYTES>>>(bs2, n);
        update_kernel<<<elemBlocks, 256>>>(n * S_DIM);
    }

    conv_finalA_kernel<<<(n * 128 + 255) / 256, 256>>>(n);
    tgemm_kernel<KO, K1, 2><<<dim3(4, gy), 256, SMEM_BYTES>>>(bo1, n);
    out_kernel<<<(n + 3) / 4, 128>>>(Wo2, bo2, m1, m2, out, n);
}